// round 4
// baseline (speedup 1.0000x reference)
#include <cuda_runtime.h>
#include <cstddef>

// Problem constants: B=256, L=20, V=9488, S=18
#define BB 256
#define LL 20
#define VV 9488
#define SS 18
#define TLEN (LL - 1)   // 19

// Scratch (no device allocation allowed)
__device__ float        g_psum[BB];
__device__ int          g_pcnt[BB];
__device__ unsigned int g_done = 0;   // block-completion counter (self-resetting)

// One warp per batch row; last finishing block reduces all partials.
__global__ __launch_bounds__(32, 32)
void scst_onepass_kernel(const float* __restrict__ inp,
                         const int*   __restrict__ tgt,
                         const float* __restrict__ reward,
                         const float* __restrict__ reward1,
                         float* __restrict__ out) {
    const int b    = blockIdx.x;
    const int lane = threadIdx.x;

    // padded target value at position j: target[b][j] for j<S, else 0 (j=18 is pad)
    int tv = 0;
    if (lane < SS) tv = tgt[b * SS + lane];

    const bool     active = (lane < TLEN);
    const unsigned zball  = __ballot_sync(0xFFFFFFFFu, active && (tv == 0));

    float val = 0.0f;
    int   cnt = 0;
    if (active) {
        const unsigned incl = (2u << lane) - 1u;   // bits 0..lane
        if (__popc(zball & incl) <= 1) {
            cnt = 1;
            val = inp[(size_t)b * (size_t)(LL * VV)
                    + (size_t)(lane + 1) * (size_t)VV
                    + (size_t)tv];
        }
    }

    // warp reduction
    #pragma unroll
    for (int off = 16; off > 0; off >>= 1) {
        val += __shfl_down_sync(0xFFFFFFFFu, val, off);
        cnt += __shfl_down_sync(0xFFFFFFFFu, cnt, off);
    }

    // publish partials + arrive on counter (lane 0), broadcast "am I last" uniformly
    unsigned prev = 0;
    if (lane == 0) {
        g_psum[b] = val;
        g_pcnt[b] = cnt;
        __threadfence();                               // release partials
        prev = atomicAdd(&g_done, 1u);
    }
    prev = __shfl_sync(0xFFFFFFFFu, prev, 0);          // ALL lanes participate
    const bool last = (prev == (unsigned)(BB - 1));

    if (last) {
        __threadfence();                               // acquire: order after counter read
        float v = 0.0f;
        int   c = 0;
        #pragma unroll
        for (int r = 0; r < BB / 32; r++) {
            const int i = r * 32 + lane;
            v += *((volatile float*)&g_psum[i]);
            c += *((volatile int*)&g_pcnt[i]);
        }
        #pragma unroll
        for (int off = 16; off > 0; off >>= 1) {
            v += __shfl_down_sync(0xFFFFFFFFu, v, off);
            c += __shfl_down_sync(0xFFFFFFFFu, c, off);
        }
        if (lane == 0) {
            float rd = reward[0] - reward1[0];
            if (rd < 1.0f) rd = 1.0f;
            out[0] = -(v / (float)c) * rd;
            __threadfence();
            g_done = 0;                                // reset for next graph replay
        }
    }
}

extern "C" void kernel_launch(void* const* d_in, const int* in_sizes, int n_in,
                              void* d_out, int out_size) {
    const float* inp     = (const float*)d_in[0];   // [B, L, V] f32
    const int*   tgt     = (const int*)  d_in[1];   // [B, S]    i32
    const float* reward  = (const float*)d_in[2];   // [1]       f32
    const float* reward1 = (const float*)d_in[3];   // [1]       f32
    float*       out     = (float*)d_out;           // [1]       f32

    scst_onepass_kernel<<<BB, 32>>>(inp, tgt, reward, reward1, out);
}

// round 5
// speedup vs baseline: 1.2694x; 1.2694x over previous
#include <cuda_runtime.h>
#include <cstddef>

// Problem constants: B=256, L=20, V=9488, S=18
#define BB 256
#define LL 20
#define VV 9488
#define SS 18
#define TLEN (LL - 1)        // 19
#define NBLK 32
#define WARPS_PER_BLK 8      // 32 blocks * 8 warps = 256 rows

// Scratch (no device allocation allowed)
__device__ float        g_psum[NBLK];
__device__ int          g_pcnt[NBLK];
__device__ unsigned int g_done = 0;   // block-completion counter (self-resetting)

__global__ __launch_bounds__(NBLK * 0 + 256, 1)
void scst_onepass_kernel(const float* __restrict__ inp,
                         const int*   __restrict__ tgt,
                         const float* __restrict__ reward,
                         const float* __restrict__ reward1,
                         float* __restrict__ out) {
    const int tid  = threadIdx.x;
    const int w    = tid >> 5;                 // warp in block: 0..7
    const int lane = tid & 31;
    const int b    = blockIdx.x * WARPS_PER_BLK + w;   // batch row 0..255

    // padded target at position j: target[b][j] for j<S(18), else 0 (j=18 is pad)
    int tv = 0;
    if (lane < SS) tv = tgt[b * SS + lane];

    const bool     active = (lane < TLEN);
    const unsigned zball  = __ballot_sync(0xFFFFFFFFu, active && (tv == 0));

    float val = 0.0f;
    int   cnt = 0;
    if (active) {
        const unsigned incl = (2u << lane) - 1u;       // inclusive bits 0..lane
        if (__popc(zball & incl) <= 1) {
            cnt = 1;
            val = inp[(size_t)b * (size_t)(LL * VV)
                    + (size_t)(lane + 1) * (size_t)VV
                    + (size_t)tv];
        }
    }

    // warp reduction
    #pragma unroll
    for (int off = 16; off > 0; off >>= 1) {
        val += __shfl_down_sync(0xFFFFFFFFu, val, off);
        cnt += __shfl_down_sync(0xFFFFFFFFu, cnt, off);
    }

    // block reduction: 8 warp partials -> 1
    __shared__ float sv[WARPS_PER_BLK];
    __shared__ int   sc[WARPS_PER_BLK];
    if (lane == 0) { sv[w] = val; sc[w] = cnt; }
    __syncthreads();

    if (w == 0) {
        float bv = (lane < WARPS_PER_BLK) ? sv[lane] : 0.0f;
        int   bc = (lane < WARPS_PER_BLK) ? sc[lane] : 0;
        #pragma unroll
        for (int off = 4; off > 0; off >>= 1) {
            bv += __shfl_down_sync(0xFFFFFFFFu, bv, off);
            bc += __shfl_down_sync(0xFFFFFFFFu, bc, off);
        }

        // publish block partial; ONE atomic arrival per block
        unsigned prev = 0;
        if (lane == 0) {
            g_psum[blockIdx.x] = bv;
            g_pcnt[blockIdx.x] = bc;
            __threadfence();                            // release partial
            prev = atomicAdd(&g_done, 1u);
        }
        prev = __shfl_sync(0xFFFFFFFFu, prev, 0);       // uniform broadcast
        if (prev == (unsigned)(NBLK - 1)) {
            __threadfence();                            // acquire before reading partials
            float v = (lane < NBLK) ? *((volatile float*)&g_psum[lane]) : 0.0f;
            int   c = (lane < NBLK) ? *((volatile int*)&g_pcnt[lane])   : 0;
            #pragma unroll
            for (int off = 16; off > 0; off >>= 1) {
                v += __shfl_down_sync(0xFFFFFFFFu, v, off);
                c += __shfl_down_sync(0xFFFFFFFFu, c, off);
            }
            if (lane == 0) {
                float rd = reward[0] - reward1[0];
                if (rd < 1.0f) rd = 1.0f;
                out[0] = -(v / (float)c) * rd;
                __threadfence();
                g_done = 0;                             // reset for next graph replay
            }
        }
    }
}

extern "C" void kernel_launch(void* const* d_in, const int* in_sizes, int n_in,
                              void* d_out, int out_size) {
    const float* inp     = (const float*)d_in[0];   // [B, L, V] f32
    const int*   tgt     = (const int*)  d_in[1];   // [B, S]    i32
    const float* reward  = (const float*)d_in[2];   // [1]       f32
    const float* reward1 = (const float*)d_in[3];   // [1]       f32
    float*       out     = (float*)d_out;           // [1]       f32

    scst_onepass_kernel<<<NBLK, 256>>>(inp, tgt, reward, reward1, out);
}

// round 7
// speedup vs baseline: 1.6000x; 1.2605x over previous
#include <cuda_runtime.h>
#include <cstddef>
#include <cstdint>

// Problem constants: B=256, L=20, V=9488, S=18
#define BB 256
#define LL 20
#define VV 9488
#define SS 18
#define TLEN (LL - 1)        // 19
#define NBLK 32
#define WARPS_PER_BLK 8      // 32 blocks * 8 warps = 256 rows

// Scratch (no device allocation allowed)
__device__ unsigned long long g_part[NBLK];   // packed {f32 val bits, u32 cnt}
__device__ unsigned int       g_done = 0;     // self-resetting arrival counter

__device__ __forceinline__ unsigned redux_add_u32(unsigned v) {
    unsigned r;
    asm volatile("redux.sync.add.u32 %0, %1, 0xffffffff;" : "=r"(r) : "r"(v));
    return r;
}
__device__ __forceinline__ void stcg_u64(unsigned long long* p, unsigned long long v) {
    asm volatile("st.global.cg.u64 [%0], %1;" :: "l"(p), "l"(v) : "memory");
}
__device__ __forceinline__ unsigned long long ldcg_u64(const unsigned long long* p) {
    unsigned long long v;
    asm volatile("ld.global.cg.u64 %0, [%1];" : "=l"(v) : "l"(p) : "memory");
    return v;
}
__device__ __forceinline__ unsigned atom_add_acqrel_gpu(unsigned* p, unsigned v) {
    unsigned old;
    asm volatile("atom.acq_rel.gpu.global.add.u32 %0, [%1], %2;"
                 : "=r"(old) : "l"(p), "r"(v) : "memory");
    return old;
}

__global__ __launch_bounds__(256, 1)
void scst_onepass_kernel(const float* __restrict__ inp,
                         const int*   __restrict__ tgt,
                         const float* __restrict__ reward,
                         const float* __restrict__ reward1,
                         float* __restrict__ out) {
    const int tid  = threadIdx.x;
    const int w    = tid >> 5;                          // warp 0..7
    const int lane = tid & 31;
    const int b    = blockIdx.x * WARPS_PER_BLK + w;    // batch row

    // Prefetch rewards early (used only by warp 0 lane 0 in the tail;
    // load issued here so the ~L2/DRAM latency overlaps the gather phase)
    float rw = 0.0f, rw1 = 0.0f;
    if (tid == 0) { rw = reward[0]; rw1 = reward1[0]; }

    // padded target at position j: target[b][j] for j<18, else 0 (j=18 is pad)
    int tv = 0;
    if (lane < SS) tv = tgt[b * SS + lane];

    const bool     active = (lane < TLEN);
    const unsigned zball  = __ballot_sync(0xFFFFFFFFu, active && (tv == 0));

    // kept set is the prefix {0..cnt-1}: cnt = index of 2nd zero, else 19
    const unsigned z2  = zball & (zball - 1u);          // clear lowest set bit
    const unsigned cnt = z2 ? (unsigned)(__ffs((int)z2) - 1) : (unsigned)TLEN;

    float val = 0.0f;
    if ((unsigned)lane < cnt) {
        val = inp[(size_t)b * (size_t)(LL * VV)
                + (size_t)(lane + 1) * (size_t)VV
                + (size_t)tv];
    }

    // warp float sum: 5 shfls (cnt needs no reduce — it's ballot-derived, uniform)
    #pragma unroll
    for (int off = 16; off > 0; off >>= 1)
        val += __shfl_down_sync(0xFFFFFFFFu, val, off);

    // block reduction: 8 warp partials -> 1
    __shared__ float    sv[WARPS_PER_BLK];
    __shared__ unsigned sc[WARPS_PER_BLK];
    if (lane == 0) { sv[w] = val; sc[w] = cnt; }
    __syncthreads();

    if (w == 0) {
        float    bv = (lane < WARPS_PER_BLK) ? sv[lane] : 0.0f;
        unsigned bc = (lane < WARPS_PER_BLK) ? sc[lane] : 0u;
        #pragma unroll
        for (int off = 4; off > 0; off >>= 1)           // only 8 live lanes: 3 shfls
            bv += __shfl_down_sync(0xFFFFFFFFu, bv, off);
        bc = redux_add_u32(bc);                         // 1 HW instr

        // publish packed partial straight to L2, then one acq_rel arrival
        unsigned prev = 0;
        if (lane == 0) {
            unsigned long long pk =
                (unsigned long long)__float_as_uint(bv) |
                ((unsigned long long)bc << 32);
            stcg_u64(&g_part[blockIdx.x], pk);
            prev = atom_add_acqrel_gpu(&g_done, 1u);
        }
        prev = __shfl_sync(0xFFFFFFFFu, prev, 0);

        if (prev == (unsigned)(NBLK - 1)) {
            // last block: fold 32 packed partials (one per lane)
            const unsigned long long pk = ldcg_u64(&g_part[lane]);
            float    v = __uint_as_float((unsigned)(pk & 0xFFFFFFFFull));
            unsigned c = (unsigned)(pk >> 32);
            #pragma unroll
            for (int off = 16; off > 0; off >>= 1)
                v += __shfl_down_sync(0xFFFFFFFFu, v, off);
            c = redux_add_u32(c);
            if (lane == 0) {
                float rd = rw - rw1;
                if (rd < 1.0f) rd = 1.0f;
                out[0] = -(v / (float)c) * rd;
                g_done = 0;   // ordered before next replay by kernel boundary
            }
        }
    }
}

extern "C" void kernel_launch(void* const* d_in, const int* in_sizes, int n_in,
                              void* d_out, int out_size) {
    const float* inp     = (const float*)d_in[0];   // [B, L, V] f32
    const int*   tgt     = (const int*)  d_in[1];   // [B, S]    i32
    const float* reward  = (const float*)d_in[2];   // [1]       f32
    const float* reward1 = (const float*)d_in[3];   // [1]       f32
    float*       out     = (float*)d_out;           // [1]       f32

    scst_onepass_kernel<<<NBLK, 256>>>(inp, tgt, reward, reward1, out);
}